// round 14
// baseline (speedup 1.0000x reference)
#include <cuda_runtime.h>
#include <cstdint>

// CustomRNN: B=64, T=512, D=U=1024
//   h = tanh(X @ W1 + b1)                      [parallel GEMM, tf32 mma]
//   y_t = h_t + tanh(y_{t-1} @ W2 + b2)        [512 sequential steps, persistent kernel]
//   out = y @ Wc + bc                          [folded, direct store]
//
// R14 OUTPUT-STATIONARY recurrence: CTA (g,c) g=0..3, c=0..31 owns pre rows
// [16g,16g+16) x cols [32c,32c+32), computing the FULL K=1024 contraction with
// its W2 slab [1024x32] resident in smem. NO atomics (plain STG partial->full
// sums), sync = 4 INDEPENDENT 32-CTA groups (one counter each), double-buffered
// pre (WAR safe via the poll: >=32t => all group reads at t-1 complete), no
// zeroing, no fixed-point. (g,c==0) CTAs own full y rows => direct out stores.

#define T_STEPS 512
#define BATCH   64
#define DIM     1024
#define NCTA    128
#define NGROUP  4       // batch groups of 16 rows
#define GCTA    32      // CTAs (col slabs) per group
#define NRANGE  32      // cols per CTA
#define W2S_STR 1036    // smem row stride (floats), conflict-free (1036%32=12)
#define YS_STR  1036

// ---------------- device scratch (allocation-free contract) ----------------
__device__ float g_h[T_STEPS * BATCH * DIM];       // h[t][b][u], 134 MB
__device__ float g_preF[2][BATCH * DIM];           // double-buffered pre (plain fp32)
__device__ unsigned int g_ctr[NGROUP];             // per-group step counters

// ---------------- helpers ----------------
__device__ __forceinline__ uint32_t f2tf_bits(float x) {
    uint32_t r;
    asm("cvt.rna.tf32.f32 %0, %1;" : "=r"(r) : "f"(x));
    return r;
}
__device__ __forceinline__ float f2tf(float x) { return __uint_as_float(f2tf_bits(x)); }

// accurate tanh for proj (off critical path)
__device__ __forceinline__ float fast_tanh(float x) {
    float e, r;
    asm("ex2.approx.f32 %0, %1;" : "=f"(e) : "f"(x * 2.8853900817779268f));
    asm("rcp.approx.f32 %0, %1;" : "=f"(r) : "f"(e + 1.0f));
    return 1.0f - 2.0f * r;
}
// hardware tanh (1 MUFU) — recurrence
__device__ __forceinline__ float tanh_hw(float x) {
    float r;
    asm("tanh.approx.f32 %0, %1;" : "=f"(r) : "f"(x));
    return r;
}

// release-arrive / acquire-poll
__device__ __forceinline__ void arrive_release(unsigned int* p) {
    asm volatile("red.release.gpu.global.add.u32 [%0], 1;" :: "l"(p) : "memory");
}
__device__ __forceinline__ unsigned int load_acquire(unsigned int* p) {
    unsigned int v;
    asm volatile("ld.acquire.gpu.global.u32 %0, [%1];" : "=r"(v) : "l"(p) : "memory");
    return v;
}
__device__ __forceinline__ void poll_ge(unsigned int* p, unsigned int target) {
    while (load_acquire(p) < target) { }
}

__device__ __forceinline__ void mma8(float c[4], uint32_t a0, uint32_t a1, uint32_t a2, uint32_t a3,
                                     uint32_t b0, uint32_t b1) {
    asm volatile(
        "mma.sync.aligned.m16n8k8.row.col.f32.tf32.tf32.f32 "
        "{%0,%1,%2,%3},{%4,%5,%6,%7},{%8,%9},{%0,%1,%2,%3};\n"
        : "+f"(c[0]), "+f"(c[1]), "+f"(c[2]), "+f"(c[3])
        : "r"(a0), "r"(a1), "r"(a2), "r"(a3), "r"(b0), "r"(b1));
}

// ---------------- phase 1: h = tanh(X @ W1 + b1), tf32 mma -----------------
// Unchanged GEMM; init: zero pre buffer 0 + group counters.
__global__ __launch_bounds__(256) void proj_kernel(const float* __restrict__ X,
                                                   const float* __restrict__ W1,
                                                   const float* __restrict__ b1) {
    __shared__ float As[2][128][20];
    __shared__ float Bs[2][16][136];

    const int tid = threadIdx.x;
    {
        const int flat = (blockIdx.y * gridDim.x + blockIdx.x) * 256 + tid;
        if (flat < BATCH * DIM / 4)
            ((float4*)&g_preF[0][0])[flat] = make_float4(0.f, 0.f, 0.f, 0.f);
        if (flat < NGROUP) g_ctr[flat] = 0u;
    }

    const int lane = tid & 31, wid = tid >> 5;
    const int g = lane >> 2, tg = lane & 3;
    const int wm0 = (wid >> 2) * 64, wn0 = (wid & 3) * 32;
    const int mbase = blockIdx.y * 128, nbase = blockIdx.x * 128;

    const int a_row0 = tid >> 2;
    const int a_row1 = a_row0 + 64;
    const int a_kq = (tid & 3) * 4;
    const int b_row0 = tid >> 5;
    const int b_row1 = b_row0 + 8;
    const int b_nq = (tid & 31) * 4;

    float acc[4][4][4];
#pragma unroll
    for (int mt = 0; mt < 4; mt++)
#pragma unroll
        for (int nt = 0; nt < 4; nt++)
#pragma unroll
            for (int i = 0; i < 4; i++) acc[mt][nt][i] = 0.0f;

    float4 ra0 = *(const float4*)&X[(mbase + a_row0) * DIM + a_kq];
    float4 ra1 = *(const float4*)&X[(mbase + a_row1) * DIM + a_kq];
    float4 rb0 = *(const float4*)&W1[b_row0 * DIM + nbase + b_nq];
    float4 rb1 = *(const float4*)&W1[b_row1 * DIM + nbase + b_nq];
    {
        float4 v;
        v.x = f2tf(ra0.x); v.y = f2tf(ra0.y); v.z = f2tf(ra0.z); v.w = f2tf(ra0.w);
        *(float4*)&As[0][a_row0][a_kq] = v;
        v.x = f2tf(ra1.x); v.y = f2tf(ra1.y); v.z = f2tf(ra1.z); v.w = f2tf(ra1.w);
        *(float4*)&As[0][a_row1][a_kq] = v;
        v.x = f2tf(rb0.x); v.y = f2tf(rb0.y); v.z = f2tf(rb0.z); v.w = f2tf(rb0.w);
        *(float4*)&Bs[0][b_row0][b_nq] = v;
        v.x = f2tf(rb1.x); v.y = f2tf(rb1.y); v.z = f2tf(rb1.z); v.w = f2tf(rb1.w);
        *(float4*)&Bs[0][b_row1][b_nq] = v;
    }
    __syncthreads();

    for (int it = 0; it < 64; ++it) {
        const int cur = it & 1;
        if (it + 1 < 64) {
            const int kk = (it + 1) * 16;
            ra0 = *(const float4*)&X[(mbase + a_row0) * DIM + kk + a_kq];
            ra1 = *(const float4*)&X[(mbase + a_row1) * DIM + kk + a_kq];
            rb0 = *(const float4*)&W1[(kk + b_row0) * DIM + nbase + b_nq];
            rb1 = *(const float4*)&W1[(kk + b_row1) * DIM + nbase + b_nq];
        }
#pragma unroll
        for (int ks = 0; ks < 2; ++ks) {
            const int k = ks * 8;
            uint32_t af[4][4], bf[4][2];
#pragma unroll
            for (int mt = 0; mt < 4; mt++) {
                const int r = wm0 + mt * 16 + g;
                af[mt][0] = __float_as_uint(As[cur][r][k + tg]);
                af[mt][1] = __float_as_uint(As[cur][r + 8][k + tg]);
                af[mt][2] = __float_as_uint(As[cur][r][k + tg + 4]);
                af[mt][3] = __float_as_uint(As[cur][r + 8][k + tg + 4]);
            }
#pragma unroll
            for (int nt = 0; nt < 4; nt++) {
                const int c = wn0 + nt * 8 + g;
                bf[nt][0] = __float_as_uint(Bs[cur][k + tg][c]);
                bf[nt][1] = __float_as_uint(Bs[cur][k + tg + 4][c]);
            }
#pragma unroll
            for (int mt = 0; mt < 4; mt++)
#pragma unroll
                for (int nt = 0; nt < 4; nt++)
                    mma8(acc[mt][nt], af[mt][0], af[mt][1], af[mt][2], af[mt][3],
                         bf[nt][0], bf[nt][1]);
        }
        __syncthreads();
        if (it + 1 < 64) {
            const int nxt = cur ^ 1;
            float4 v;
            v.x = f2tf(ra0.x); v.y = f2tf(ra0.y); v.z = f2tf(ra0.z); v.w = f2tf(ra0.w);
            *(float4*)&As[nxt][a_row0][a_kq] = v;
            v.x = f2tf(ra1.x); v.y = f2tf(ra1.y); v.z = f2tf(ra1.z); v.w = f2tf(ra1.w);
            *(float4*)&As[nxt][a_row1][a_kq] = v;
            v.x = f2tf(rb0.x); v.y = f2tf(rb0.y); v.z = f2tf(rb0.z); v.w = f2tf(rb0.w);
            *(float4*)&Bs[nxt][b_row0][b_nq] = v;
            v.x = f2tf(rb1.x); v.y = f2tf(rb1.y); v.z = f2tf(rb1.z); v.w = f2tf(rb1.w);
            *(float4*)&Bs[nxt][b_row1][b_nq] = v;
            __syncthreads();
        }
    }

#pragma unroll
    for (int nt = 0; nt < 4; nt++) {
        const int c = nbase + wn0 + nt * 8 + tg * 2;
        const float bb0 = b1[c], bb1 = b1[c + 1];
#pragma unroll
        for (int mt = 0; mt < 4; mt++) {
            const int r = mbase + wm0 + mt * 16 + g;
            {
                float2 v;
                v.x = fast_tanh(acc[mt][nt][0] + bb0);
                v.y = fast_tanh(acc[mt][nt][1] + bb1);
                const int t = r & 511, b = r >> 9;
                *(float2*)&g_h[(t * 64 + b) * DIM + c] = v;
            }
            {
                const int r2 = r + 8;
                float2 v;
                v.x = fast_tanh(acc[mt][nt][2] + bb0);
                v.y = fast_tanh(acc[mt][nt][3] + bb1);
                const int t = r2 & 511, b = r2 >> 9;
                *(float2*)&g_h[(t * 64 + b) * DIM + c] = v;
            }
        }
    }
}

// ---------------- phase 2: output-stationary recurrence --------------------
// CTA (grp, c): rows [16grp,16grp+16), cols [32c,32c+32). 256 threads.
// Warp w builds y rows 2w,2w+1 (h held in-place in ys, prefetched by same
// warp); GEMM: warp w = N-tile (w&3) x K-half (w>>2), 64 mma, 2 acc chains;
// warps 4-7 stage accs in smem; warps 0-3 pair-reduce + STG to nxt.
// Release per group; (grp, c==0) stores out rows directly.
__global__ __launch_bounds__(256, 1) void recur_kernel(const float* __restrict__ W2,
                                                       const float* __restrict__ b2,
                                                       const float* __restrict__ Wc,
                                                       const float* __restrict__ bc,
                                                       float* __restrict__ out) {
    extern __shared__ float sm[];
    float* W2s = sm;                     // [32][W2S_STR] n-major, tf32-rounded
    float* ys  = W2s + 32 * W2S_STR;     // [16][YS_STR]  y rows (h in-place)
    float* accs= ys + 16 * YS_STR;       // [4*32*4] staged partner accs
    float* b2s = accs + 512;             // [1024]
    float* Wcs = b2s + 1024;             // [1024]

    const int tid = threadIdx.x, lane = tid & 31, wid = tid >> 5;
    const int g = lane >> 2, tg = lane & 3;
    const int cid = blockIdx.x;
    const int grp = cid >> 5, c = cid & 31;
    const int rbase = grp * 16, nbase = c * NRANGE;
    const int nt = wid & 3, kh = wid >> 2, kb = kh * 512;
    const float bc0 = bc[0];

    // W2 slab [1024 k][32 n] -> smem n-major, tf32-rounded
    for (int i = tid; i < 32 * DIM; i += 256) {
        const int n = i & 31, k = i >> 5;
        W2s[n * W2S_STR + k] = f2tf(W2[k * DIM + nbase + n]);
    }
    for (int i = tid; i < DIM; i += 256) { b2s[i] = b2[i]; Wcs[i] = Wc[i]; }

    // prologue: h(0) rows into ys (warp w owns rows 2w, 2w+1)
#pragma unroll
    for (int j = 0; j < 2; ++j) {
        const int gr = rbase + 2 * wid + j;
#pragma unroll
        for (int i = 0; i < 8; ++i) {
            const int col = lane * 4 + i * 128;
            *(float4*)&ys[(2 * wid + j) * YS_STR + col] =
                *(const float4*)&g_h[(size_t)gr * DIM + col];
        }
    }
    __syncthreads();

    for (int t = 0; t < T_STEPS; ++t) {
        const float* pre = g_preF[t & 1];
        float* nxt = g_preF[(t + 1) & 1];

        // (a) wait own group's 32 CTAs to finish step t-1
        if (t > 0) {
            if (tid == 0) poll_ge(&g_ctr[grp], (unsigned)t * 32u);
        }
        __syncthreads();   // bar A: broadcast acquire

        // (b) build own 2 y rows: y = tf32(h + tanh(pre + b2)); h in ys, in-place
#pragma unroll
        for (int j = 0; j < 2; ++j) {
            const int lr = 2 * wid + j;
            const int gr = rbase + lr;
#pragma unroll
            for (int i = 0; i < 8; ++i) {
                const int col = lane * 4 + i * 128;
                const float4 p = *(const float4*)&pre[gr * DIM + col];
                const float4 h4 = *(const float4*)&ys[lr * YS_STR + col];
                const float4 bb = *(const float4*)&b2s[col];
                float4 y;
                y.x = f2tf(h4.x + tanh_hw(p.x + bb.x));
                y.y = f2tf(h4.y + tanh_hw(p.y + bb.y));
                y.z = f2tf(h4.z + tanh_hw(p.z + bb.z));
                y.w = f2tf(h4.w + tanh_hw(p.w + bb.w));
                *(float4*)&ys[lr * YS_STR + col] = y;
            }
        }
        __syncthreads();   // bar B: y visible CTA-wide

        // (c) GEMM: warp tile 16(M) x 8(N) over K-half 512; 2 interleaved chains
        float accA[4] = {0.f, 0.f, 0.f, 0.f};
        float accB[4] = {0.f, 0.f, 0.f, 0.f};
        const int coln = nt * 8 + g;
#pragma unroll
        for (int ks = 0; ks < 32; ++ks) {
            const int k0 = kb + ks * 16;
            {
                const uint32_t a0 = __float_as_uint(ys[g * YS_STR + k0 + tg]);
                const uint32_t a1 = __float_as_uint(ys[(g + 8) * YS_STR + k0 + tg]);
                const uint32_t a2 = __float_as_uint(ys[g * YS_STR + k0 + tg + 4]);
                const uint32_t a3 = __float_as_uint(ys[(g + 8) * YS_STR + k0 + tg + 4]);
                const uint32_t b0 = __float_as_uint(W2s[coln * W2S_STR + k0 + tg]);
                const uint32_t b1v = __float_as_uint(W2s[coln * W2S_STR + k0 + tg + 4]);
                mma8(accA, a0, a1, a2, a3, b0, b1v);
            }
            {
                const int k1 = k0 + 8;
                const uint32_t a0 = __float_as_uint(ys[g * YS_STR + k1 + tg]);
                const uint32_t a1 = __float_as_uint(ys[(g + 8) * YS_STR + k1 + tg]);
                const uint32_t a2 = __float_as_uint(ys[g * YS_STR + k1 + tg + 4]);
                const uint32_t a3 = __float_as_uint(ys[(g + 8) * YS_STR + k1 + tg + 4]);
                const uint32_t b0 = __float_as_uint(W2s[coln * W2S_STR + k1 + tg]);
                const uint32_t b1v = __float_as_uint(W2s[coln * W2S_STR + k1 + tg + 4]);
                mma8(accB, a0, a1, a2, a3, b0, b1v);
            }
        }
#pragma unroll
        for (int i = 0; i < 4; ++i) accA[i] += accB[i];

        // (d) K-half 1 warps stage accs
        if (kh == 1) {
#pragma unroll
            for (int i = 0; i < 4; ++i) accs[(nt * 32 + lane) * 4 + i] = accA[i];
        }
        __syncthreads();   // bar C: stages visible; all GEMM ys-reads complete

        // (e) K-half 0 warps reduce + plain STG to nxt (no atomics)
        if (kh == 0) {
#pragma unroll
            for (int i = 0; i < 4; ++i) accA[i] += accs[(nt * 32 + lane) * 4 + i];
            const int gr = rbase + g;
            const int col = nbase + nt * 8 + tg * 2;
            *(float2*)&nxt[gr * DIM + col]       = make_float2(accA[0], accA[1]);
            *(float2*)&nxt[(gr + 8) * DIM + col] = make_float2(accA[2], accA[3]);
        }

        // (f) publish to own group
        __syncthreads();   // bar D: STGs ordered to tid0
        if (tid == 0) arrive_release(&g_ctr[grp]);

        // ---- off-chain tail (own rows only; no other CTA awaits this) ----

        // (g) direct output: (grp, c==0) dots its full y rows with Wc
        if (c == 0) {
#pragma unroll
            for (int j = 0; j < 2; ++j) {
                const int lr = 2 * wid + j;
                float s = 0.0f;
#pragma unroll
                for (int i = 0; i < 8; ++i) {
                    const int col = lane * 4 + i * 128;
                    const float4 yv = *(const float4*)&ys[lr * YS_STR + col];
                    const float4 wv = *(const float4*)&Wcs[col];
                    s += yv.x * wv.x + yv.y * wv.y + yv.z * wv.z + yv.w * wv.w;
                }
                s += __shfl_xor_sync(0xffffffffu, s, 16);
                s += __shfl_xor_sync(0xffffffffu, s, 8);
                s += __shfl_xor_sync(0xffffffffu, s, 4);
                s += __shfl_xor_sync(0xffffffffu, s, 2);
                s += __shfl_xor_sync(0xffffffffu, s, 1);
                if (lane == 0) out[(rbase + lr) * T_STEPS + t] = s + bc0;
            }
        }

        // (h) prefetch h(t+1) into ys in-place (same warp, same rows; reads of
        //     ys by GEMM ended before bar C; own Wc dot precedes in prog order)
        {
            const int tn = (t + 1 < T_STEPS) ? (t + 1) : t;
            const float* hn = g_h + (size_t)tn * BATCH * DIM;
#pragma unroll
            for (int j = 0; j < 2; ++j) {
                const int lr = 2 * wid + j;
                const int gr = rbase + lr;
#pragma unroll
                for (int i = 0; i < 8; ++i) {
                    const int col = lane * 4 + i * 128;
                    *(float4*)&ys[lr * YS_STR + col] =
                        *(const float4*)&hn[gr * DIM + col];
                }
            }
        }
    }
}

// ---------------- launch ----------------
extern "C" void kernel_launch(void* const* d_in, const int* in_sizes, int n_in,
                              void* d_out, int out_size) {
    const float* X  = (const float*)d_in[0];
    const float* W1 = (const float*)d_in[1];
    const float* b1 = (const float*)d_in[2];
    const float* W2 = (const float*)d_in[3];
    const float* b2 = (const float*)d_in[4];
    const float* Wc = (const float*)d_in[5];
    const float* bc = (const float*)d_in[6];
    float* out = (float*)d_out;

    // smem: 32*1036 + 16*1036 + 512 + 1024 + 1024 floats = 52,288 * 4 = 209,152 B
    const int recur_smem = (32 * W2S_STR + 16 * YS_STR + 512 + 1024 + 1024) * 4;
    cudaFuncSetAttribute(recur_kernel, cudaFuncAttributeMaxDynamicSharedMemorySize, recur_smem);

    proj_kernel<<<dim3(8, 256), 256>>>(X, W1, b1);
    recur_kernel<<<NCTA, 256, recur_smem>>>(W2, b2, Wc, bc, out);
}

// round 16
// speedup vs baseline: 1.2873x; 1.2873x over previous
#include <cuda_runtime.h>
#include <cstdint>

// CustomRNN: B=64, T=512, D=U=1024
//   h = tanh(X @ W1 + b1)                      [parallel GEMM, tf32 mma]
//   y_t = h_t + tanh(y_{t-1} @ W2 + b2)        [512 sequential steps, persistent kernel]
//   out = y @ Wc + bc                          [folded into recurrence]
//
// Recurrence: 8 K-chunks x 16 N-chunks = 128 CTAs, dep-sync. R16:
//   * red.global.add.v4.f32 with shfl-pair column gather: 4 RED ops/thread
//     (was 8) -> LSU issue floor (4cyc/op/SMSP) cost halves.
//   * per-producer release FLAGS (st.release to private 128B lines) + 16-way
//     parallel acquire-poll: kills the 16-way same-address atomic arrival
//     serialization of the old shared counters.
//   * RING=6 (was 5): the tail zero of buffer (t-2)%6 is next RED-target at
//     step t+3, whose writers transitively require all CTAs' t+1 completions
//     — releases issued AFTER the zero. Closes the latent R13/R15 WAR race
//     while keeping the zero off the critical chain.

#define T_STEPS 512
#define BATCH   64
#define DIM     1024
#define NCTA    128
#define KC_N    8
#define NC_N    16
#define KRANGE  128
#define NRANGE  64
#define RING    6

// ---------------- device scratch (allocation-free contract) ----------------
__device__ float g_h[T_STEPS * BATCH * DIM];        // h[t][b][u], 134 MB
__device__ float g_pre[RING][BATCH * DIM];          // rotating fp32 pre buffers
__device__ float g_outp[T_STEPS * KC_N * BATCH];    // partial Wc dots [t][kc][b]
__device__ unsigned int g_flag[NC_N][KC_N * 32];    // per-producer step flags (128B apart)
__device__ unsigned int g_bar;                      // final (epilogue) barrier

// ---------------- helpers ----------------
__device__ __forceinline__ uint32_t f2tf_bits(float x) {
    uint32_t r;
    asm("cvt.rna.tf32.f32 %0, %1;" : "=r"(r) : "f"(x));
    return r;
}
__device__ __forceinline__ float f2tf(float x) { return __uint_as_float(f2tf_bits(x)); }

// accurate tanh for proj (off critical path)
__device__ __forceinline__ float fast_tanh(float x) {
    float e, r;
    asm("ex2.approx.f32 %0, %1;" : "=f"(e) : "f"(x * 2.8853900817779268f));
    asm("rcp.approx.f32 %0, %1;" : "=f"(r) : "f"(e + 1.0f));
    return 1.0f - 2.0f * r;
}
// hardware tanh (1 MUFU) — recurrence only
__device__ __forceinline__ float tanh_hw(float x) {
    float r;
    asm("tanh.approx.f32 %0, %1;" : "=f"(r) : "f"(x));
    return r;
}

// 128-bit no-return global reduction (4 fp32 lanes, 1 LSU op)
__device__ __forceinline__ void red_add_v4(float* p, float a, float b, float c, float d) {
    asm volatile("red.global.add.v4.f32 [%0], {%1, %2, %3, %4};"
                 :: "l"(p), "f"(a), "f"(b), "f"(c), "f"(d) : "memory");
}

// release/acquire primitives
__device__ __forceinline__ void store_release(unsigned int* p, unsigned int v) {
    asm volatile("st.release.gpu.global.u32 [%0], %1;" :: "l"(p), "r"(v) : "memory");
}
__device__ __forceinline__ void arrive_release(unsigned int* p) {
    asm volatile("red.release.gpu.global.add.u32 [%0], 1;" :: "l"(p) : "memory");
}
__device__ __forceinline__ unsigned int load_acquire(unsigned int* p) {
    unsigned int v;
    asm volatile("ld.acquire.gpu.global.u32 %0, [%1];" : "=r"(v) : "l"(p) : "memory");
    return v;
}
__device__ __forceinline__ void poll_ge(unsigned int* p, unsigned int target) {
    while (load_acquire(p) < target) { }
}

__device__ __forceinline__ void mma8(float c[4], uint32_t a0, uint32_t a1, uint32_t a2, uint32_t a3,
                                     uint32_t b0, uint32_t b1) {
    asm volatile(
        "mma.sync.aligned.m16n8k8.row.col.f32.tf32.tf32.f32 "
        "{%0,%1,%2,%3},{%4,%5,%6,%7},{%8,%9},{%0,%1,%2,%3};\n"
        : "+f"(c[0]), "+f"(c[1]), "+f"(c[2]), "+f"(c[3])
        : "r"(a0), "r"(a1), "r"(a2), "r"(a3), "r"(b0), "r"(b1));
}

// ---------------- phase 1: h = tanh(X @ W1 + b1), tf32 mma -----------------
__global__ __launch_bounds__(256) void proj_kernel(const float* __restrict__ X,
                                                   const float* __restrict__ W1,
                                                   const float* __restrict__ b1) {
    __shared__ float As[2][128][20];
    __shared__ float Bs[2][16][136];

    const int tid = threadIdx.x;
    {
        const int flat = (blockIdx.y * gridDim.x + blockIdx.x) * 256 + tid;
        if (flat < RING * BATCH * DIM / 4)
            ((float4*)&g_pre[0][0])[flat] = make_float4(0.f, 0.f, 0.f, 0.f);
        if (flat < NC_N * KC_N * 32) ((unsigned int*)g_flag)[flat] = 0u;
        if (flat == 0) g_bar = 0u;
    }

    const int lane = tid & 31, wid = tid >> 5;
    const int g = lane >> 2, tg = lane & 3;
    const int wm0 = (wid >> 2) * 64, wn0 = (wid & 3) * 32;
    const int mbase = blockIdx.y * 128, nbase = blockIdx.x * 128;

    const int a_row0 = tid >> 2;
    const int a_row1 = a_row0 + 64;
    const int a_kq = (tid & 3) * 4;
    const int b_row0 = tid >> 5;
    const int b_row1 = b_row0 + 8;
    const int b_nq = (tid & 31) * 4;

    float acc[4][4][4];
#pragma unroll
    for (int mt = 0; mt < 4; mt++)
#pragma unroll
        for (int nt = 0; nt < 4; nt++)
#pragma unroll
            for (int i = 0; i < 4; i++) acc[mt][nt][i] = 0.0f;

    float4 ra0 = *(const float4*)&X[(mbase + a_row0) * DIM + a_kq];
    float4 ra1 = *(const float4*)&X[(mbase + a_row1) * DIM + a_kq];
    float4 rb0 = *(const float4*)&W1[b_row0 * DIM + nbase + b_nq];
    float4 rb1 = *(const float4*)&W1[b_row1 * DIM + nbase + b_nq];
    {
        float4 v;
        v.x = f2tf(ra0.x); v.y = f2tf(ra0.y); v.z = f2tf(ra0.z); v.w = f2tf(ra0.w);
        *(float4*)&As[0][a_row0][a_kq] = v;
        v.x = f2tf(ra1.x); v.y = f2tf(ra1.y); v.z = f2tf(ra1.z); v.w = f2tf(ra1.w);
        *(float4*)&As[0][a_row1][a_kq] = v;
        v.x = f2tf(rb0.x); v.y = f2tf(rb0.y); v.z = f2tf(rb0.z); v.w = f2tf(rb0.w);
        *(float4*)&Bs[0][b_row0][b_nq] = v;
        v.x = f2tf(rb1.x); v.y = f2tf(rb1.y); v.z = f2tf(rb1.z); v.w = f2tf(rb1.w);
        *(float4*)&Bs[0][b_row1][b_nq] = v;
    }
    __syncthreads();

    for (int it = 0; it < 64; ++it) {
        const int cur = it & 1;
        if (it + 1 < 64) {
            const int kk = (it + 1) * 16;
            ra0 = *(const float4*)&X[(mbase + a_row0) * DIM + kk + a_kq];
            ra1 = *(const float4*)&X[(mbase + a_row1) * DIM + kk + a_kq];
            rb0 = *(const float4*)&W1[(kk + b_row0) * DIM + nbase + b_nq];
            rb1 = *(const float4*)&W1[(kk + b_row1) * DIM + nbase + b_nq];
        }
#pragma unroll
        for (int ks = 0; ks < 2; ++ks) {
            const int k = ks * 8;
            uint32_t af[4][4], bf[4][2];
#pragma unroll
            for (int mt = 0; mt < 4; mt++) {
                const int r = wm0 + mt * 16 + g;
                af[mt][0] = __float_as_uint(As[cur][r][k + tg]);
                af[mt][1] = __float_as_uint(As[cur][r + 8][k + tg]);
                af[mt][2] = __float_as_uint(As[cur][r][k + tg + 4]);
                af[mt][3] = __float_as_uint(As[cur][r + 8][k + tg + 4]);
            }
#pragma unroll
            for (int nt = 0; nt < 4; nt++) {
                const int c = wn0 + nt * 8 + g;
                bf[nt][0] = __float_as_uint(Bs[cur][k + tg][c]);
                bf[nt][1] = __float_as_uint(Bs[cur][k + tg + 4][c]);
            }
#pragma unroll
            for (int mt = 0; mt < 4; mt++)
#pragma unroll
                for (int nt = 0; nt < 4; nt++)
                    mma8(acc[mt][nt], af[mt][0], af[mt][1], af[mt][2], af[mt][3],
                         bf[nt][0], bf[nt][1]);
        }
        __syncthreads();
        if (it + 1 < 64) {
            const int nxt = cur ^ 1;
            float4 v;
            v.x = f2tf(ra0.x); v.y = f2tf(ra0.y); v.z = f2tf(ra0.z); v.w = f2tf(ra0.w);
            *(float4*)&As[nxt][a_row0][a_kq] = v;
            v.x = f2tf(ra1.x); v.y = f2tf(ra1.y); v.z = f2tf(ra1.z); v.w = f2tf(ra1.w);
            *(float4*)&As[nxt][a_row1][a_kq] = v;
            v.x = f2tf(rb0.x); v.y = f2tf(rb0.y); v.z = f2tf(rb0.z); v.w = f2tf(rb0.w);
            *(float4*)&Bs[nxt][b_row0][b_nq] = v;
            v.x = f2tf(rb1.x); v.y = f2tf(rb1.y); v.z = f2tf(rb1.z); v.w = f2tf(rb1.w);
            *(float4*)&Bs[nxt][b_row1][b_nq] = v;
            __syncthreads();
        }
    }

#pragma unroll
    for (int nt = 0; nt < 4; nt++) {
        const int c = nbase + wn0 + nt * 8 + tg * 2;
        const float bb0 = b1[c], bb1 = b1[c + 1];
#pragma unroll
        for (int mt = 0; mt < 4; mt++) {
            const int r = mbase + wm0 + mt * 16 + g;
            {
                float2 v;
                v.x = fast_tanh(acc[mt][nt][0] + bb0);
                v.y = fast_tanh(acc[mt][nt][1] + bb1);
                const int t = r & 511, b = r >> 9;
                *(float2*)&g_h[(t * 64 + b) * DIM + c] = v;
            }
            {
                const int r2 = r + 8;
                float2 v;
                v.x = fast_tanh(acc[mt][nt][2] + bb0);
                v.y = fast_tanh(acc[mt][nt][3] + bb1);
                const int t = r2 & 511, b = r2 >> 9;
                *(float2*)&g_h[(t * 64 + b) * DIM + c] = v;
            }
        }
    }
}

// ---------------- phase 2: persistent recurrence ---------------------------
__global__ __launch_bounds__(256, 1) void recur_kernel(const float* __restrict__ W2,
                                                       const float* __restrict__ b2,
                                                       const float* __restrict__ Wc,
                                                       const float* __restrict__ bc,
                                                       float* __restrict__ out) {
    extern __shared__ float sm[];
    float* W2s = sm;                  // [64][132], n-major, tf32-rounded
    float* ys  = sm + 64 * 132;       // [64][132]
    float* b2s = ys + 64 * 132;       // [128]
    float* Wcs = b2s + 128;           // [128]

    const int tid = threadIdx.x, lane = tid & 31, wid = tid >> 5;
    const int g = lane >> 2, tg = lane & 3;
    const int pair = wid >> 1, sub = wid & 1;
    const int m0 = pair * 16, n0 = sub * 32;
    const int rb0 = pair * 16 + sub * 8;     // this warp builds rows rb0..rb0+7
    const int cid = blockIdx.x;
    const int kc = cid >> 4, nc = cid & 15;
    const int kbase = kc * KRANGE, nbase = nc * NRANGE;

    for (int i = tid; i < NRANGE * KRANGE; i += 256) {
        const int n = i & 63, k = i >> 6;
        W2s[n * 132 + k] = f2tf(W2[(kbase + k) * DIM + nbase + n]);
    }
    if (tid < 128) { b2s[tid] = b2[kbase + tid]; Wcs[tid] = Wc[kbase + tid]; }
    __syncthreads();

    // prologue: prefetch h rows for t=0
    float4 hreg[8];
#pragma unroll
    for (int j = 0; j < 8; ++j)
        hreg[j] = *(const float4*)&g_h[(size_t)(rb0 + j) * DIM + kbase + lane * 4];

    for (int t = 0; t < T_STEPS; ++t) {
        const float* pre = g_pre[t % RING];
        float* nxt = g_pre[(t + 1) % RING];
        float* zb  = g_pre[(t + 4) % RING];   // == (t-2) mod RING (RING=6)

        // (a) wait my 16 producers' step t-1 flags (16 parallel pollers)
        if (t > 0) {
            if (tid < 16) {
                const int pnc = 2 * kc + (tid >> 3);   // producer nc'
                const int pkc = tid & 7;               // producer kc'
                poll_ge(&g_flag[pnc][pkc * 32], (unsigned)t);
            }
        }
        __syncthreads();   // broadcast acquire

        // (b) build own 8 y rows: y = tf32(h + tanh(pre + b2))
        float4 preg[8];
#pragma unroll
        for (int j = 0; j < 8; ++j)
            preg[j] = *(const float4*)&pre[(rb0 + j) * DIM + kbase + lane * 4];
#pragma unroll
        for (int j = 0; j < 8; ++j) {
            float4 y;
            y.x = f2tf(hreg[j].x + tanh_hw(preg[j].x + b2s[lane * 4 + 0]));
            y.y = f2tf(hreg[j].y + tanh_hw(preg[j].y + b2s[lane * 4 + 1]));
            y.z = f2tf(hreg[j].z + tanh_hw(preg[j].z + b2s[lane * 4 + 2]));
            y.w = f2tf(hreg[j].w + tanh_hw(preg[j].w + b2s[lane * 4 + 3]));
            *(float4*)&ys[(rb0 + j) * 132 + lane * 4] = y;
        }
        __syncthreads();   // builds visible CTA-wide

        // (c) GEMM in two N-halves; each half's v4 REDs issue immediately
        float acc[4][4];
#pragma unroll
        for (int nt = 0; nt < 4; nt++)
#pragma unroll
            for (int i = 0; i < 4; i++) acc[nt][i] = 0.0f;

#pragma unroll
        for (int half = 0; half < 2; ++half) {
#pragma unroll
            for (int ks = 0; ks < 16; ++ks) {
                const int k = ks * 8;
                const uint32_t a0 = __float_as_uint(ys[(m0 + g) * 132 + k + tg]);
                const uint32_t a1 = __float_as_uint(ys[(m0 + g + 8) * 132 + k + tg]);
                const uint32_t a2 = __float_as_uint(ys[(m0 + g) * 132 + k + tg + 4]);
                const uint32_t a3 = __float_as_uint(ys[(m0 + g + 8) * 132 + k + tg + 4]);
#pragma unroll
                for (int nh = 0; nh < 2; ++nh) {
                    const int nt = half * 2 + nh;
                    const int col = n0 + nt * 8 + g;
                    const uint32_t b0 = __float_as_uint(W2s[col * 132 + k + tg]);
                    const uint32_t b1v = __float_as_uint(W2s[col * 132 + k + tg + 4]);
                    mma8(acc[nt], a0, a1, a2, a3, b0, b1v);
                }
            }
            // v4 REDs for this half: shfl-pair so each thread owns 4 contiguous
            // cols of one row. even tg -> row m0+g, odd tg -> row m0+g+8.
#pragma unroll
            for (int nh = 0; nh < 2; ++nh) {
                const int nt = half * 2 + nh;
                const float p0 = __shfl_xor_sync(0xffffffffu, acc[nt][0], 1);
                const float p1 = __shfl_xor_sync(0xffffffffu, acc[nt][1], 1);
                const float p2 = __shfl_xor_sync(0xffffffffu, acc[nt][2], 1);
                const float p3 = __shfl_xor_sync(0xffffffffu, acc[nt][3], 1);
                const int cb = nbase + n0 + nt * 8;
                if ((tg & 1) == 0) {
                    // cols 2tg..2tg+3 of row m0+g  (tg=0 -> 0..3, tg=2 -> 4..7)
                    red_add_v4(&nxt[(m0 + g) * DIM + cb + 2 * tg],
                               acc[nt][0], acc[nt][1], p0, p1);
                } else {
                    // cols 2(tg-1)..2(tg-1)+3 of row m0+g+8
                    red_add_v4(&nxt[(m0 + g + 8) * DIM + cb + 2 * (tg - 1)],
                               p2, p3, acc[nt][2], acc[nt][3]);
                }
            }
        }

        // (d) publish step t: my flag (private 128B line, plain store-release)
        __syncthreads();   // REDs ordered to tid0
        if (tid == 0) store_release(&g_flag[nc][kc * 32], (unsigned)(t + 1));

        // ---- off-chain tail ----

        // (e) zero flat slab of the step t-2 buffer. RING=6: next REDs into it
        //     happen at t+3, whose writers transitively require all CTAs' t+1
        //     completions — releases issued AFTER this zero. Race-free.
        if (tid < 128)
            ((float4*)zb)[cid * 128 + tid] = make_float4(0.f, 0.f, 0.f, 0.f);

        // (f) prefetch h for step t+1 (immutable)
        {
            const int tn = (t + 1 < T_STEPS) ? (t + 1) : t;
            const float* hn = g_h + (size_t)tn * BATCH * DIM;
#pragma unroll
            for (int j = 0; j < 8; ++j)
                hreg[j] = *(const float4*)&hn[(rb0 + j) * DIM + kbase + lane * 4];
        }

        // (g) folded output projection on own rows (nc==0 CTAs only)
        if (nc == 0) {
#pragma unroll
            for (int j = 0; j < 8; ++j) {
                const float4 yv = *(const float4*)&ys[(rb0 + j) * 132 + lane * 4];
                const float4 wv = *(const float4*)&Wcs[lane * 4];
                float s = yv.x * wv.x + yv.y * wv.y + yv.z * wv.z + yv.w * wv.w;
                s += __shfl_xor_sync(0xffffffffu, s, 16);
                s += __shfl_xor_sync(0xffffffffu, s, 8);
                s += __shfl_xor_sync(0xffffffffu, s, 4);
                s += __shfl_xor_sync(0xffffffffu, s, 2);
                s += __shfl_xor_sync(0xffffffffu, s, 1);
                if (lane == 0) g_outp[t * (KC_N * BATCH) + kc * BATCH + rb0 + j] = s;
            }
        }
    }

    // final full-grid barrier (orders last-step g_outp stores), then epilogue
    __syncthreads();
    if (tid == 0) {
        arrive_release(&g_bar);
        if (cid < 32) poll_ge(&g_bar, NCTA);
    }
    __syncthreads();
    if (cid < 32) {
        const float bias = bc[0];
#pragma unroll
        for (int i = 0; i < 4; ++i) {
            const int idx = cid * 1024 + tid * 4 + i;   // 0..32767
            const int b = idx >> 9, tt = idx & 511;
            float s = bias;
#pragma unroll
            for (int k2 = 0; k2 < KC_N; k2++)
                s += g_outp[tt * (KC_N * BATCH) + k2 * BATCH + b];
            out[idx] = s;
        }
    }
}

// ---------------- launch ----------------
extern "C" void kernel_launch(void* const* d_in, const int* in_sizes, int n_in,
                              void* d_out, int out_size) {
    const float* X  = (const float*)d_in[0];
    const float* W1 = (const float*)d_in[1];
    const float* b1 = (const float*)d_in[2];
    const float* W2 = (const float*)d_in[3];
    const float* b2 = (const float*)d_in[4];
    const float* Wc = (const float*)d_in[5];
    const float* bc = (const float*)d_in[6];
    float* out = (float*)d_out;

    const int recur_smem = (64 * 132 + 64 * 132 + 128 + 128) * 4;  // 68608 B
    cudaFuncSetAttribute(recur_kernel, cudaFuncAttributeMaxDynamicSharedMemorySize, recur_smem);

    proj_kernel<<<dim3(8, 256), 256>>>(X, W1, b1);
    recur_kernel<<<NCTA, 256, recur_smem>>>(W2, b2, Wc, bc, out);
}

// round 17
// speedup vs baseline: 1.3867x; 1.0772x over previous
#include <cuda_runtime.h>
#include <cstdint>

// CustomRNN: B=64, T=512, D=U=1024
//   h = tanh(X @ W1 + b1)                      [parallel GEMM, tf32 mma]
//   y_t = h_t + tanh(y_{t-1} @ W2 + b2)        [512 sequential steps, persistent kernel]
//   out = y @ Wc + bc                          [folded into recurrence]
//
// R17: TWO INDEPENDENT 32-ROW HALVES, 2 CTAs/SM. 256 CTAs = 2 x (8kc x 16nc),
// each half a full copy of the R16 dep-sync structure (per-producer release
// flags, shfl-pair red.v4.f32, RING=6 lag-bound zeroing) over its own 32 batch
// rows. Per-CTA compute halves; the 2 co-resident CTAs' chains interleave on
// the SM so latency segments of one hide behind compute of the other.

#define T_STEPS 512
#define BATCH   64
#define DIM     1024
#define NCTA    256
#define HALVES  2
#define HB      32      // batch rows per half
#define KC_N    8
#define NC_N    16
#define KRANGE  128
#define NRANGE  64
#define RING    6

// ---------------- device scratch (allocation-free contract) ----------------
__device__ float g_h[T_STEPS * BATCH * DIM];          // h[t][b][u], 134 MB
__device__ float g_pre[RING][BATCH * DIM];            // rotating fp32 pre buffers
__device__ float g_outp[T_STEPS * KC_N * BATCH];      // partial Wc dots [t][kc][b]
__device__ unsigned int g_flag[HALVES][NC_N][KC_N * 32]; // per-producer flags (128B apart)
__device__ unsigned int g_bar;                        // final (epilogue) barrier

// ---------------- helpers ----------------
__device__ __forceinline__ uint32_t f2tf_bits(float x) {
    uint32_t r;
    asm("cvt.rna.tf32.f32 %0, %1;" : "=r"(r) : "f"(x));
    return r;
}
__device__ __forceinline__ float f2tf(float x) { return __uint_as_float(f2tf_bits(x)); }

// accurate tanh for proj (off critical path)
__device__ __forceinline__ float fast_tanh(float x) {
    float e, r;
    asm("ex2.approx.f32 %0, %1;" : "=f"(e) : "f"(x * 2.8853900817779268f));
    asm("rcp.approx.f32 %0, %1;" : "=f"(r) : "f"(e + 1.0f));
    return 1.0f - 2.0f * r;
}
// hardware tanh (1 MUFU) — recurrence only
__device__ __forceinline__ float tanh_hw(float x) {
    float r;
    asm("tanh.approx.f32 %0, %1;" : "=f"(r) : "f"(x));
    return r;
}

// 128-bit no-return global reduction (4 fp32 lanes, 1 LSU op)
__device__ __forceinline__ void red_add_v4(float* p, float a, float b, float c, float d) {
    asm volatile("red.global.add.v4.f32 [%0], {%1, %2, %3, %4};"
                 :: "l"(p), "f"(a), "f"(b), "f"(c), "f"(d) : "memory");
}

// release/acquire primitives
__device__ __forceinline__ void store_release(unsigned int* p, unsigned int v) {
    asm volatile("st.release.gpu.global.u32 [%0], %1;" :: "l"(p), "r"(v) : "memory");
}
__device__ __forceinline__ void arrive_release(unsigned int* p) {
    asm volatile("red.release.gpu.global.add.u32 [%0], 1;" :: "l"(p) : "memory");
}
__device__ __forceinline__ unsigned int load_acquire(unsigned int* p) {
    unsigned int v;
    asm volatile("ld.acquire.gpu.global.u32 %0, [%1];" : "=r"(v) : "l"(p) : "memory");
    return v;
}
__device__ __forceinline__ void poll_ge(unsigned int* p, unsigned int target) {
    while (load_acquire(p) < target) { }
}

__device__ __forceinline__ void mma8(float c[4], uint32_t a0, uint32_t a1, uint32_t a2, uint32_t a3,
                                     uint32_t b0, uint32_t b1) {
    asm volatile(
        "mma.sync.aligned.m16n8k8.row.col.f32.tf32.tf32.f32 "
        "{%0,%1,%2,%3},{%4,%5,%6,%7},{%8,%9},{%0,%1,%2,%3};\n"
        : "+f"(c[0]), "+f"(c[1]), "+f"(c[2]), "+f"(c[3])
        : "r"(a0), "r"(a1), "r"(a2), "r"(a3), "r"(b0), "r"(b1));
}

// ---------------- phase 1: h = tanh(X @ W1 + b1), tf32 mma -----------------
__global__ __launch_bounds__(256) void proj_kernel(const float* __restrict__ X,
                                                   const float* __restrict__ W1,
                                                   const float* __restrict__ b1) {
    __shared__ float As[2][128][20];
    __shared__ float Bs[2][16][136];

    const int tid = threadIdx.x;
    {
        const int flat = (blockIdx.y * gridDim.x + blockIdx.x) * 256 + tid;
        if (flat < RING * BATCH * DIM / 4)
            ((float4*)&g_pre[0][0])[flat] = make_float4(0.f, 0.f, 0.f, 0.f);
        if (flat < HALVES * NC_N * KC_N * 32) ((unsigned int*)g_flag)[flat] = 0u;
        if (flat == 0) g_bar = 0u;
    }

    const int lane = tid & 31, wid = tid >> 5;
    const int g = lane >> 2, tg = lane & 3;
    const int wm0 = (wid >> 2) * 64, wn0 = (wid & 3) * 32;
    const int mbase = blockIdx.y * 128, nbase = blockIdx.x * 128;

    const int a_row0 = tid >> 2;
    const int a_row1 = a_row0 + 64;
    const int a_kq = (tid & 3) * 4;
    const int b_row0 = tid >> 5;
    const int b_row1 = b_row0 + 8;
    const int b_nq = (tid & 31) * 4;

    float acc[4][4][4];
#pragma unroll
    for (int mt = 0; mt < 4; mt++)
#pragma unroll
        for (int nt = 0; nt < 4; nt++)
#pragma unroll
            for (int i = 0; i < 4; i++) acc[mt][nt][i] = 0.0f;

    float4 ra0 = *(const float4*)&X[(mbase + a_row0) * DIM + a_kq];
    float4 ra1 = *(const float4*)&X[(mbase + a_row1) * DIM + a_kq];
    float4 rb0 = *(const float4*)&W1[b_row0 * DIM + nbase + b_nq];
    float4 rb1 = *(const float4*)&W1[b_row1 * DIM + nbase + b_nq];
    {
        float4 v;
        v.x = f2tf(ra0.x); v.y = f2tf(ra0.y); v.z = f2tf(ra0.z); v.w = f2tf(ra0.w);
        *(float4*)&As[0][a_row0][a_kq] = v;
        v.x = f2tf(ra1.x); v.y = f2tf(ra1.y); v.z = f2tf(ra1.z); v.w = f2tf(ra1.w);
        *(float4*)&As[0][a_row1][a_kq] = v;
        v.x = f2tf(rb0.x); v.y = f2tf(rb0.y); v.z = f2tf(rb0.z); v.w = f2tf(rb0.w);
        *(float4*)&Bs[0][b_row0][b_nq] = v;
        v.x = f2tf(rb1.x); v.y = f2tf(rb1.y); v.z = f2tf(rb1.z); v.w = f2tf(rb1.w);
        *(float4*)&Bs[0][b_row1][b_nq] = v;
    }
    __syncthreads();

    for (int it = 0; it < 64; ++it) {
        const int cur = it & 1;
        if (it + 1 < 64) {
            const int kk = (it + 1) * 16;
            ra0 = *(const float4*)&X[(mbase + a_row0) * DIM + kk + a_kq];
            ra1 = *(const float4*)&X[(mbase + a_row1) * DIM + kk + a_kq];
            rb0 = *(const float4*)&W1[(kk + b_row0) * DIM + nbase + b_nq];
            rb1 = *(const float4*)&W1[(kk + b_row1) * DIM + nbase + b_nq];
        }
#pragma unroll
        for (int ks = 0; ks < 2; ++ks) {
            const int k = ks * 8;
            uint32_t af[4][4], bf[4][2];
#pragma unroll
            for (int mt = 0; mt < 4; mt++) {
                const int r = wm0 + mt * 16 + g;
                af[mt][0] = __float_as_uint(As[cur][r][k + tg]);
                af[mt][1] = __float_as_uint(As[cur][r + 8][k + tg]);
                af[mt][2] = __float_as_uint(As[cur][r][k + tg + 4]);
                af[mt][3] = __float_as_uint(As[cur][r + 8][k + tg + 4]);
            }
#pragma unroll
            for (int nt = 0; nt < 4; nt++) {
                const int c = wn0 + nt * 8 + g;
                bf[nt][0] = __float_as_uint(Bs[cur][k + tg][c]);
                bf[nt][1] = __float_as_uint(Bs[cur][k + tg + 4][c]);
            }
#pragma unroll
            for (int mt = 0; mt < 4; mt++)
#pragma unroll
                for (int nt = 0; nt < 4; nt++)
                    mma8(acc[mt][nt], af[mt][0], af[mt][1], af[mt][2], af[mt][3],
                         bf[nt][0], bf[nt][1]);
        }
        __syncthreads();
        if (it + 1 < 64) {
            const int nxt = cur ^ 1;
            float4 v;
            v.x = f2tf(ra0.x); v.y = f2tf(ra0.y); v.z = f2tf(ra0.z); v.w = f2tf(ra0.w);
            *(float4*)&As[nxt][a_row0][a_kq] = v;
            v.x = f2tf(ra1.x); v.y = f2tf(ra1.y); v.z = f2tf(ra1.z); v.w = f2tf(ra1.w);
            *(float4*)&As[nxt][a_row1][a_kq] = v;
            v.x = f2tf(rb0.x); v.y = f2tf(rb0.y); v.z = f2tf(rb0.z); v.w = f2tf(rb0.w);
            *(float4*)&Bs[nxt][b_row0][b_nq] = v;
            v.x = f2tf(rb1.x); v.y = f2tf(rb1.y); v.z = f2tf(rb1.z); v.w = f2tf(rb1.w);
            *(float4*)&Bs[nxt][b_row1][b_nq] = v;
            __syncthreads();
        }
    }

#pragma unroll
    for (int nt = 0; nt < 4; nt++) {
        const int c = nbase + wn0 + nt * 8 + tg * 2;
        const float bb0 = b1[c], bb1 = b1[c + 1];
#pragma unroll
        for (int mt = 0; mt < 4; mt++) {
            const int r = mbase + wm0 + mt * 16 + g;
            {
                float2 v;
                v.x = fast_tanh(acc[mt][nt][0] + bb0);
                v.y = fast_tanh(acc[mt][nt][1] + bb1);
                const int t = r & 511, b = r >> 9;
                *(float2*)&g_h[(t * 64 + b) * DIM + c] = v;
            }
            {
                const int r2 = r + 8;
                float2 v;
                v.x = fast_tanh(acc[mt][nt][2] + bb0);
                v.y = fast_tanh(acc[mt][nt][3] + bb1);
                const int t = r2 & 511, b = r2 >> 9;
                *(float2*)&g_h[(t * 64 + b) * DIM + c] = v;
            }
        }
    }
}

// ---------------- phase 2: persistent recurrence (2 halves, 2 CTAs/SM) ----
// CTA cid: half = cid>>7, c = cid&127, kc = c>>4, nc = c&15.
// Rows [32*half, 32*half+32). Warp roles: build rows rb0=wid*4 (4 each);
// GEMM warp tile 16(M: (wid&1)*16) x 16(N: (wid>>1)*16) x 128(K).
__global__ __launch_bounds__(256, 2) void recur_kernel(const float* __restrict__ W2,
                                                       const float* __restrict__ b2,
                                                       const float* __restrict__ Wc,
                                                       const float* __restrict__ bc,
                                                       float* __restrict__ out) {
    extern __shared__ float sm[];
    float* W2s = sm;                  // [64][132], n-major, tf32-rounded
    float* ys  = sm + 64 * 132;       // [32][132]
    float* b2s = ys + 32 * 132;       // [128]
    float* Wcs = b2s + 128;           // [128]

    const int tid = threadIdx.x, lane = tid & 31, wid = tid >> 5;
    const int g = lane >> 2, tg = lane & 3;
    const int cid = blockIdx.x;
    const int half = cid >> 7, c = cid & 127;
    const int kc = c >> 4, nc = c & 15;
    const int kbase = kc * KRANGE, nbase = nc * NRANGE;
    const int rbase = half * HB;
    const int m0 = (wid & 1) * 16;       // local M tile
    const int n0 = (wid >> 1) * 16;      // local N tile
    const int rb0 = wid * 4;             // local build rows rb0..rb0+3

    for (int i = tid; i < NRANGE * KRANGE; i += 256) {
        const int n = i & 63, k = i >> 6;
        W2s[n * 132 + k] = f2tf(W2[(kbase + k) * DIM + nbase + n]);
    }
    if (tid < 128) { b2s[tid] = b2[kbase + tid]; Wcs[tid] = Wc[kbase + tid]; }
    __syncthreads();

    // prologue: prefetch h rows for t=0 (4 local rows per warp)
    float4 hreg[4];
#pragma unroll
    for (int j = 0; j < 4; ++j)
        hreg[j] = *(const float4*)&g_h[(size_t)(rbase + rb0 + j) * DIM + kbase + lane * 4];

    for (int t = 0; t < T_STEPS; ++t) {
        const float* pre = g_pre[t % RING];
        float* nxt = g_pre[(t + 1) % RING];
        float* zb  = g_pre[(t + 4) % RING];   // == (t-2) mod RING (RING=6)

        // (a) wait my half's 16 producers' step t-1 flags (16 parallel pollers)
        if (t > 0) {
            if (tid < 16) {
                const int pnc = 2 * kc + (tid >> 3);
                const int pkc = tid & 7;
                poll_ge(&g_flag[half][pnc][pkc * 32], (unsigned)t);
            }
        }
        __syncthreads();   // broadcast acquire

        // (b) build own 4 y rows: y = tf32(h + tanh(pre + b2))
        float4 preg[4];
#pragma unroll
        for (int j = 0; j < 4; ++j)
            preg[j] = *(const float4*)&pre[(rbase + rb0 + j) * DIM + kbase + lane * 4];
#pragma unroll
        for (int j = 0; j < 4; ++j) {
            float4 y;
            y.x = f2tf(hreg[j].x + tanh_hw(preg[j].x + b2s[lane * 4 + 0]));
            y.y = f2tf(hreg[j].y + tanh_hw(preg[j].y + b2s[lane * 4 + 1]));
            y.z = f2tf(hreg[j].z + tanh_hw(preg[j].z + b2s[lane * 4 + 2]));
            y.w = f2tf(hreg[j].w + tanh_hw(preg[j].w + b2s[lane * 4 + 3]));
            *(float4*)&ys[(rb0 + j) * 132 + lane * 4] = y;
        }
        __syncthreads();   // builds visible CTA-wide

        // (c) GEMM: warp tile 16(M) x 16(N) x 128(K) -> 32 mma
        float acc[2][4];
#pragma unroll
        for (int nt = 0; nt < 2; nt++)
#pragma unroll
            for (int i = 0; i < 4; i++) acc[nt][i] = 0.0f;

#pragma unroll
        for (int ks = 0; ks < 16; ++ks) {
            const int k = ks * 8;
            const uint32_t a0 = __float_as_uint(ys[(m0 + g) * 132 + k + tg]);
            const uint32_t a1 = __float_as_uint(ys[(m0 + g + 8) * 132 + k + tg]);
            const uint32_t a2 = __float_as_uint(ys[(m0 + g) * 132 + k + tg + 4]);
            const uint32_t a3 = __float_as_uint(ys[(m0 + g + 8) * 132 + k + tg + 4]);
#pragma unroll
            for (int nt = 0; nt < 2; ++nt) {
                const int col = n0 + nt * 8 + g;
                const uint32_t b0 = __float_as_uint(W2s[col * 132 + k + tg]);
                const uint32_t b1v = __float_as_uint(W2s[col * 132 + k + tg + 4]);
                mma8(acc[nt], a0, a1, a2, a3, b0, b1v);
            }
        }

        // (d) shfl-pair v4 REDs: even tg -> row rbase+m0+g, odd -> +8
#pragma unroll
        for (int nt = 0; nt < 2; ++nt) {
            const float p0 = __shfl_xor_sync(0xffffffffu, acc[nt][0], 1);
            const float p1 = __shfl_xor_sync(0xffffffffu, acc[nt][1], 1);
            const float p2 = __shfl_xor_sync(0xffffffffu, acc[nt][2], 1);
            const float p3 = __shfl_xor_sync(0xffffffffu, acc[nt][3], 1);
            const int cb = nbase + n0 + nt * 8;
            if ((tg & 1) == 0) {
                red_add_v4(&nxt[(rbase + m0 + g) * DIM + cb + 2 * tg],
                           acc[nt][0], acc[nt][1], p0, p1);
            } else {
                red_add_v4(&nxt[(rbase + m0 + g + 8) * DIM + cb + 2 * (tg - 1)],
                           p2, p3, acc[nt][2], acc[nt][3]);
            }
        }

        // (e) publish step t (private 128B flag line, store-release)
        __syncthreads();   // REDs ordered to tid0
        if (tid == 0) store_release(&g_flag[half][nc][kc * 32], (unsigned)(t + 1));

        // ---- off-chain tail ----

        // (f) zero own slab of step t-2 buffer, own half's rows only.
        //     RING=6: next REDs into it at t+3 require all half-CTAs' t+1
        //     completions, whose releases are issued AFTER this zero.
        if (tid < 64)
            ((float4*)zb)[half * 8192 + c * 64 + tid] = make_float4(0.f, 0.f, 0.f, 0.f);

        // (g) prefetch h for step t+1 (immutable)
        {
            const int tn = (t + 1 < T_STEPS) ? (t + 1) : t;
            const float* hn = g_h + (size_t)tn * BATCH * DIM;
#pragma unroll
            for (int j = 0; j < 4; ++j)
                hreg[j] = *(const float4*)&hn[(rbase + rb0 + j) * DIM + kbase + lane * 4];
        }

        // (h) folded output projection on own rows (nc==0 CTAs only)
        if (nc == 0) {
#pragma unroll
            for (int j = 0; j < 4; ++j) {
                const float4 yv = *(const float4*)&ys[(rb0 + j) * 132 + lane * 4];
                const float4 wv = *(const float4*)&Wcs[lane * 4];
                float s = yv.x * wv.x + yv.y * wv.y + yv.z * wv.z + yv.w * wv.w;
                s += __shfl_xor_sync(0xffffffffu, s, 16);
                s += __shfl_xor_sync(0xffffffffu, s, 8);
                s += __shfl_xor_sync(0xffffffffu, s, 4);
                s += __shfl_xor_sync(0xffffffffu, s, 2);
                s += __shfl_xor_sync(0xffffffffu, s, 1);
                if (lane == 0)
                    g_outp[t * (KC_N * BATCH) + kc * BATCH + rbase + rb0 + j] = s;
            }
        }
    }

    // final full-grid barrier (orders last-step g_outp stores), then epilogue
    __syncthreads();
    if (tid == 0) {
        arrive_release(&g_bar);
        if (cid < 32) poll_ge(&g_bar, NCTA);
    }
    __syncthreads();
    if (cid < 32) {
        const float bias = bc[0];
#pragma unroll
        for (int i = 0; i < 4; ++i) {
            const int idx = cid * 1024 + tid * 4 + i;   // 0..32767
            const int b = idx >> 9, tt = idx & 511;
            float s = bias;
#pragma unroll
            for (int k2 = 0; k2 < KC_N; k2++)
                s += g_outp[tt * (KC_N * BATCH) + k2 * BATCH + b];
            out[idx] = s;
        }
    }
}

// ---------------- launch ----------------
extern "C" void kernel_launch(void* const* d_in, const int* in_sizes, int n_in,
                              void* d_out, int out_size) {
    const float* X  = (const float*)d_in[0];
    const float* W1 = (const float*)d_in[1];
    const float* b1 = (const float*)d_in[2];
    const float* W2 = (const float*)d_in[3];
    const float* b2 = (const float*)d_in[4];
    const float* Wc = (const float*)d_in[5];
    const float* bc = (const float*)d_in[6];
    float* out = (float*)d_out;

    // smem: W2s 64*132 + ys 32*132 + b2s 128 + Wcs 128 = 12,928 floats = 51,712 B
    const int recur_smem = (64 * 132 + 32 * 132 + 128 + 128) * 4;
    cudaFuncSetAttribute(recur_kernel, cudaFuncAttributeMaxDynamicSharedMemorySize, recur_smem);

    proj_kernel<<<dim3(8, 256), 256>>>(X, W1, b1);
    recur_kernel<<<NCTA, 256, recur_smem>>>(W2, b2, Wc, bc, out);
}